// round 9
// baseline (speedup 1.0000x reference)
#include <cuda_runtime.h>
#include <cstdint>

#define BB 32
#define SS 8192
#define DD 64
#define FF 128
#define CS 64
#define NCH (SS / CS)   // 128 chunks

// Cross-CTA scan state (flags zeroed each launch)
__device__ float g_aggA[NCH * BB * FF];
__device__ float g_aggC[NCH * BB * FF];
__device__ int   g_flag[NCH * BB];

__global__ void zero_flags()
{
    const int i = blockIdx.x * 256 + threadIdx.x;
    if (i < NCH * BB) g_flag[i] = 0;
}

// SMEM float offsets (total 28928 floats = 113 KB -> 2 CTAs/SM)
#define SMW   0        // W: 64 k-rows x 128 cols              8192
#define SME0  8192     // E slab 0: 32 k x 64 s (pitch 68)     2176
#define SME1  10368    // E slab 1                             2176
#define SMA   12544    // A  (k_s -> cumsum): 64 x 128         8192
#define SMV   20736    // VC (v_f, c -> cumsum): 64 x 128      8192
#define SMPF  8192     // prefbuf A (reuses SME0)
#define SMPFC 8320     // prefbuf C
#define SM_FLOATS 28928

// ---- packed f32x2 helpers ----
__device__ __forceinline__ uint64_t pack2(float x) {
    uint64_t r;
    asm("mov.b64 %0, {%1, %1};" : "=l"(r) : "r"(__float_as_uint(x)));
    return r;
}
__device__ __forceinline__ float2 unpack2(uint64_t v) {
    uint32_t lo, hi;
    asm("mov.b64 {%0, %1}, %2;" : "=r"(lo), "=r"(hi) : "l"(v));
    return make_float2(__uint_as_float(lo), __uint_as_float(hi));
}
#define FMA2(d, a, b) \
    asm("fma.rn.f32x2 %0, %1, %2, %0;" : "+l"(d) : "l"(a), "l"(b))

#define GATE(x) (((x) > 0.5f) ? (x) : 0.f)

// Load whole 64x64 input tile into xr[4]: row = tid>>2, float4-col = (tid&3)+4j
#define LOADX(xptr)                                                           \
    do {                                                                      \
        const float4* _p4 = (const float4*)(xptr);                            \
        _Pragma("unroll")                                                     \
        for (int _j = 0; _j < 4; _j++)                                        \
            xr[_j] = _p4[xbase + 4 * _j];                                     \
    } while (0)

// exp + store k-half h of xr into E slab at eb (32 k x 64 s, pitch 68)
#define STSE(h, eb)                                                           \
    do {                                                                      \
        const int _row = tid >> 2;                                            \
        _Pragma("unroll")                                                     \
        for (int _jj = 0; _jj < 2; _jj++) {                                   \
            const float4 _x = xr[2 * (h) + _jj];                              \
            const int _kb = 4 * (tid & 3) + 16 * _jj;                         \
            sm[(eb) + (_kb + 0) * 68 + _row] = __expf(_x.x);                  \
            sm[(eb) + (_kb + 1) * 68 + _row] = __expf(_x.y);                  \
            sm[(eb) + (_kb + 2) * 68 + _row] = __expf(_x.z);                  \
            sm[(eb) + (_kb + 3) * 68 + _row] = __expf(_x.w);                  \
        }                                                                     \
    } while (0)

// FFMA2 over k-half h reading E slab at eb.
// acc[r][0..1] = col pairs [tf*4,+4); acc[r][2..3] = [64+tf*4,+4). r = 0..3.
#define FMAH(h, eb)                                                           \
    do {                                                                      \
        _Pragma("unroll 8")                                                   \
        for (int _kk = 0; _kk < 32; _kk++) {                                  \
            const float4 _av = *(const float4*)&sm[(eb) + _kk * 68 + s0];     \
            const ulonglong2 _w0 = *(const ulonglong2*)&sm[SMW + ((h) * 32 + _kk) * 128 + tf * 4];      \
            const ulonglong2 _w1 = *(const ulonglong2*)&sm[SMW + ((h) * 32 + _kk) * 128 + 64 + tf * 4]; \
            const uint64_t _a0 = pack2(_av.x);                                \
            const uint64_t _a1 = pack2(_av.y);                                \
            const uint64_t _a2 = pack2(_av.z);                                \
            const uint64_t _a3 = pack2(_av.w);                                \
            FMA2(acc[0][0], _a0, _w0.x); FMA2(acc[0][1], _a0, _w0.y);         \
            FMA2(acc[0][2], _a0, _w1.x); FMA2(acc[0][3], _a0, _w1.y);         \
            FMA2(acc[1][0], _a1, _w0.x); FMA2(acc[1][1], _a1, _w0.y);         \
            FMA2(acc[1][2], _a1, _w1.x); FMA2(acc[1][3], _a1, _w1.y);         \
            FMA2(acc[2][0], _a2, _w0.x); FMA2(acc[2][1], _a2, _w0.y);         \
            FMA2(acc[2][2], _a2, _w1.x); FMA2(acc[2][3], _a2, _w1.y);         \
            FMA2(acc[3][0], _a3, _w0.x); FMA2(acc[3][1], _a3, _w0.y);         \
            FMA2(acc[3][2], _a3, _w1.x); FMA2(acc[3][3], _a3, _w1.y);         \
        }                                                                     \
    } while (0)

#define ZEROACC()                                                             \
    do {                                                                      \
        _Pragma("unroll") for (int _r = 0; _r < 4; _r++)                      \
        _Pragma("unroll") for (int _p = 0; _p < 4; _p++) acc[_r][_p] = 0ull;  \
    } while (0)

// ---------------------------------------------------------------------------
// Fused: FFMA2 feature GEMMs (double-buffered staging) + gates + two-level
// chunked scan (decoupled lookback) + output.
// CTA = 64 s-rows x 128 F, 256 threads (4x8 tile as 4 col-pairs), 2 CTAs/SM.
// Grid (BB, NCH): linear bid = ch*BB + b (chunk-major).
// ---------------------------------------------------------------------------
__global__ __launch_bounds__(256, 2)
void fused_sla(const float* __restrict__ q, const float* __restrict__ k,
               const float* __restrict__ v, const float* __restrict__ w,
               float* __restrict__ out)
{
    extern __shared__ float sm[];
    const int tid = threadIdx.x;
    const int tf  = tid & 15;
    const int s0  = (tid >> 4) * 4;
    const int b   = blockIdx.x;
    const int ch  = blockIdx.y;
    const int xbase = (tid >> 2) * 16 + (tid & 3);
    const size_t ibase = ((size_t)b * SS + ch * CS) * DD;

    float4 xr[4];
    uint64_t acc[4][4];

    LOADX(v + ibase);
    // W -> smem identity (coalesced)
#pragma unroll
    for (int t = 0; t < 8; t++)
        ((float4*)sm)[tid + t * 256] = ((const float4*)w)[tid + t * 256];
    STSE(0, SME0);
    __syncthreads();

    // ===== V GEMM =====
    ZEROACC();
    STSE(1, SME1); LOADX(k + ibase);
    FMAH(0, SME0);
    __syncthreads();
    STSE(0, SME0);               // K half0 into slab0
    FMAH(1, SME1);
#pragma unroll
    for (int i = 0; i < 4; i++) {
        const int row = s0 + i;
        ulonglong2 t0; t0.x = acc[i][0]; t0.y = acc[i][1];
        ulonglong2 t1; t1.x = acc[i][2]; t1.y = acc[i][3];
        *(ulonglong2*)&sm[SMV + row * 128 + tf * 4]      = t0;
        *(ulonglong2*)&sm[SMV + row * 128 + 64 + tf * 4] = t1;
    }
    __syncthreads();

    // ===== K GEMM =====
    ZEROACC();
    STSE(1, SME1); LOADX(q + ibase);
    FMAH(0, SME0);
    __syncthreads();
    STSE(0, SME0);               // Q half0 into slab0
    FMAH(1, SME1);
#pragma unroll
    for (int i = 0; i < 4; i++) {
        const int row = s0 + i;
        const float2 k01 = unpack2(acc[i][0]);
        const float2 k23 = unpack2(acc[i][1]);
        const float2 k45 = unpack2(acc[i][2]);
        const float2 k67 = unpack2(acc[i][3]);
        const float4 vf0 = *(const float4*)&sm[SMV + row * 128 + tf * 4];
        const float4 vf1 = *(const float4*)&sm[SMV + row * 128 + 64 + tf * 4];
        float4 a0, a1, c0, c1;
        a0.x = GATE(k01.x); a0.y = GATE(k01.y);
        a0.z = GATE(k23.x); a0.w = GATE(k23.y);
        a1.x = GATE(k45.x); a1.y = GATE(k45.y);
        a1.z = GATE(k67.x); a1.w = GATE(k67.y);
        c0.x = a0.x * vf0.x; c0.y = a0.y * vf0.y;
        c0.z = a0.z * vf0.z; c0.w = a0.w * vf0.w;
        c1.x = a1.x * vf1.x; c1.y = a1.y * vf1.y;
        c1.z = a1.z * vf1.z; c1.w = a1.w * vf1.w;
        *(float4*)&sm[SMA + row * 128 + tf * 4]      = a0;
        *(float4*)&sm[SMA + row * 128 + 64 + tf * 4] = a1;
        *(float4*)&sm[SMV + row * 128 + tf * 4]      = c0;
        *(float4*)&sm[SMV + row * 128 + 64 + tf * 4] = c1;
    }
    __syncthreads();

    // ===== local cumsums (two 32-row halves per column, in place) =====
    {
        const int col = tid & 127;
        const int r0  = (tid >> 7) * 32;
        float cA = 0.f, cC = 0.f;
#pragma unroll 8
        for (int s = 0; s < 32; s++) {
            cA += sm[SMA + (r0 + s) * 128 + col];
            sm[SMA + (r0 + s) * 128 + col] = cA;
            cC += sm[SMV + (r0 + s) * 128 + col];
            sm[SMV + (r0 + s) * 128 + col] = cC;
        }
    }
    __syncthreads();

    // ===== Q GEMM (agg publish overlapped with FMAH(0)) =====
    ZEROACC();
    if (tid < FF) {
        const float aggA = sm[SMA + 31 * 128 + tid] + sm[SMA + 63 * 128 + tid];
        const float aggC = sm[SMV + 31 * 128 + tid] + sm[SMV + 63 * 128 + tid];
        g_aggA[((size_t)ch * BB + b) * FF + tid] = aggA;
        g_aggC[((size_t)ch * BB + b) * FF + tid] = aggC;
        __threadfence();
    }
    STSE(1, SME1);
    FMAH(0, SME0);
    __syncthreads();
    if (tid == 0) atomicExch(&g_flag[ch * BB + b], 1);
    FMAH(1, SME1);

    // gate q_s into float registers
    float4 qsa[4], qsb[4];
#pragma unroll
    for (int i = 0; i < 4; i++) {
        const float2 q01 = unpack2(acc[i][0]);
        const float2 q23 = unpack2(acc[i][1]);
        const float2 q45 = unpack2(acc[i][2]);
        const float2 q67 = unpack2(acc[i][3]);
        qsa[i].x = GATE(q01.x); qsa[i].y = GATE(q01.y);
        qsa[i].z = GATE(q23.x); qsa[i].w = GATE(q23.y);
        qsb[i].x = GATE(q45.x); qsb[i].y = GATE(q45.y);
        qsb[i].z = GATE(q67.x); qsb[i].w = GATE(q67.y);
    }

    // ===== lookback wait (parallel) =====
    if (tid < ch)
        while (((volatile int*)g_flag)[tid * BB + b] == 0) __nanosleep(64);
    __syncthreads();

    // ===== prefix sums over predecessors -> prefbuf =====
    if (tid < FF) {
        float pA0 = 0.f, pA1 = 0.f, pC0 = 0.f, pC1 = 0.f;
        int p = 0;
        for (; p + 1 < ch; p += 2) {
            pA0 += g_aggA[((size_t)p * BB + b) * FF + tid];
            pA1 += g_aggA[((size_t)(p + 1) * BB + b) * FF + tid];
            pC0 += g_aggC[((size_t)p * BB + b) * FF + tid];
            pC1 += g_aggC[((size_t)(p + 1) * BB + b) * FF + tid];
        }
        if (p < ch) {
            pA0 += g_aggA[((size_t)p * BB + b) * FF + tid];
            pC0 += g_aggC[((size_t)p * BB + b) * FF + tid];
        }
        sm[SMPF  + tid] = pA0 + pA1;
        sm[SMPFC + tid] = pC0 + pC1;
    }
    __syncthreads();

    // ===== output: out = q_s * (C+eps)/(A+eps), fully parallel =====
    const size_t ob = ((size_t)b * SS + ch * CS) * FF;
    float4 bA0 = *(const float4*)&sm[SMPF + tf * 4];
    float4 bA1 = *(const float4*)&sm[SMPF + 64 + tf * 4];
    float4 bC0 = *(const float4*)&sm[SMPFC + tf * 4];
    float4 bC1 = *(const float4*)&sm[SMPFC + 64 + tf * 4];
    if (s0 >= 32) {
        const float4 lA0 = *(const float4*)&sm[SMA + 31 * 128 + tf * 4];
        const float4 lA1 = *(const float4*)&sm[SMA + 31 * 128 + 64 + tf * 4];
        const float4 lC0 = *(const float4*)&sm[SMV + 31 * 128 + tf * 4];
        const float4 lC1 = *(const float4*)&sm[SMV + 31 * 128 + 64 + tf * 4];
        bA0.x += lA0.x; bA0.y += lA0.y; bA0.z += lA0.z; bA0.w += lA0.w;
        bA1.x += lA1.x; bA1.y += lA1.y; bA1.z += lA1.z; bA1.w += lA1.w;
        bC0.x += lC0.x; bC0.y += lC0.y; bC0.z += lC0.z; bC0.w += lC0.w;
        bC1.x += lC1.x; bC1.y += lC1.y; bC1.z += lC1.z; bC1.w += lC1.w;
    }
#pragma unroll
    for (int i = 0; i < 4; i++) {
        const int row = s0 + i;
        const float4 a0 = *(const float4*)&sm[SMA + row * 128 + tf * 4];
        const float4 a1 = *(const float4*)&sm[SMA + row * 128 + 64 + tf * 4];
        const float4 c0 = *(const float4*)&sm[SMV + row * 128 + tf * 4];
        const float4 c1 = *(const float4*)&sm[SMV + row * 128 + 64 + tf * 4];
        float4 o0, o1;
        o0.x = qsa[i].x * __fdividef(bC0.x + c0.x + 1e-8f, bA0.x + a0.x + 1e-8f);
        o0.y = qsa[i].y * __fdividef(bC0.y + c0.y + 1e-8f, bA0.y + a0.y + 1e-8f);
        o0.z = qsa[i].z * __fdividef(bC0.z + c0.z + 1e-8f, bA0.z + a0.z + 1e-8f);
        o0.w = qsa[i].w * __fdividef(bC0.w + c0.w + 1e-8f, bA0.w + a0.w + 1e-8f);
        o1.x = qsb[i].x * __fdividef(bC1.x + c1.x + 1e-8f, bA1.x + a1.x + 1e-8f);
        o1.y = qsb[i].y * __fdividef(bC1.y + c1.y + 1e-8f, bA1.y + a1.y + 1e-8f);
        o1.z = qsb[i].z * __fdividef(bC1.z + c1.z + 1e-8f, bA1.z + a1.z + 1e-8f);
        o1.w = qsb[i].w * __fdividef(bC1.w + c1.w + 1e-8f, bA1.w + a1.w + 1e-8f);
        *(float4*)&out[ob + (size_t)row * FF + tf * 4]      = o0;
        *(float4*)&out[ob + (size_t)row * FF + 64 + tf * 4] = o1;
    }
}

extern "C" void kernel_launch(void* const* d_in, const int* in_sizes, int n_in,
                              void* d_out, int out_size)
{
    const float* q = (const float*)d_in[0];
    const float* k = (const float*)d_in[1];
    const float* v = (const float*)d_in[2];
    const float* w = (const float*)d_in[3];
    float* out = (float*)d_out;

    zero_flags<<<(NCH * BB + 255) / 256, 256>>>();

    cudaFuncSetAttribute(fused_sla, cudaFuncAttributeMaxDynamicSharedMemorySize,
                         SM_FLOATS * 4);
    dim3 grid(BB, NCH);   // linear bid = ch*BB + b (chunk-major)
    fused_sla<<<grid, 256, SM_FLOATS * 4>>>(q, k, v, w, out);
}

// round 10
// speedup vs baseline: 1.2614x; 1.2614x over previous
#include <cuda_runtime.h>
#include <cstdint>

#define BB 32
#define SS 8192
#define DD 64
#define FF 128
#define CS 64
#define NCH (SS / CS)   // 128 chunks

// Cross-CTA scan state (flags zeroed each launch)
__device__ float    g_aggA[NCH * BB * FF];
__device__ float    g_aggC[NCH * BB * FF];
__device__ int      g_flag[NCH * BB];
__device__ uint32_t g_wfragB[8192];   // [plane][kstep][ntile][lane][reg] packed bf16x2

__global__ void zero_flags()
{
    const int i = blockIdx.x * 256 + threadIdx.x;
    if (i < NCH * BB) g_flag[i] = 0;
}

// pack (lo, hi) fp32 -> bf16x2 (lo in lower 16 bits)
__device__ __forceinline__ uint32_t bf16x2(float lo, float hi) {
    uint32_t r;
    asm("cvt.rn.bf16x2.f32 %0, %1, %2;" : "=r"(r) : "f"(hi), "f"(lo));
    return r;
}
// split: returns big bf16x2, writes residual bf16x2
__device__ __forceinline__ uint32_t split_pack(float e0, float e1, uint32_t& sres) {
    const uint32_t b = bf16x2(e0, e1);
    const float f0 = __uint_as_float(b << 16);
    const float f1 = __uint_as_float(b & 0xFFFF0000u);
    sres = bf16x2(e0 - f0, e1 - f1);
    return b;
}

// ---------------------------------------------------------------------------
// Setup: W -> (big, small) bf16 B-fragments in gmem, m16n8k16 fragment order.
// idx = plane*4096 + kstep*1024 + ntile*64 + lane*2 + reg
// reg r holds k = kstep*16 + tig*2 + r*8 (+1), col = ntile*8 + group.
// ---------------------------------------------------------------------------
__global__ void wfrag_setup(const float* __restrict__ w)
{
    for (int o = threadIdx.x; o < 8192; o += 256) {
        const int reg = o & 1, lane = (o >> 1) & 31, nt = (o >> 6) & 15;
        const int ks = (o >> 10) & 3, plane = (o >> 12) & 1;
        const int group = lane >> 2, tig = lane & 3;
        const int k0  = ks * 16 + tig * 2 + reg * 8;
        const int col = nt * 8 + group;
        const float v0 = w[k0 * FF + col];
        const float v1 = w[(k0 + 1) * FF + col];
        uint32_t s;
        const uint32_t b = split_pack(v0, v1, s);
        g_wfragB[o] = plane ? s : b;
    }
}

// SMEM word offsets (total 28672 words = 112 KB -> 2 CTAs/SM)
#define SM_WF 0        // B frags: 8192 u32 (32 KB)
#define SM_E  8192     // A staging: EB 2048 u32 + ES 2048 u32 (16 KB, swizzled)
#define SMA   12288    // k_s -> cumsum: 64 x 128 f32 (32 KB)
#define SMV   20480    // v_f / c -> cumsum: 64 x 128 f32 (32 KB)
#define SMPF  8192     // prefix A (reuses E after Q mma)
#define SMPFC 8320     // prefix C
#define SM_FLOATS 28672
#define E_BYTE (SM_E * 4)   // 32768

#define GATE(x) (((x) > 0.5f) ? (x) : 0.f)

#define LDM4(r, a)                                                            \
    asm volatile("ldmatrix.sync.aligned.m8n8.x4.shared.b16 {%0,%1,%2,%3}, [%4];" \
        : "=r"((r)[0]), "=r"((r)[1]), "=r"((r)[2]), "=r"((r)[3]) : "r"(a))

#define MMAB(c, a, bb)                                                        \
    asm volatile("mma.sync.aligned.m16n8k16.row.col.f32.bf16.bf16.f32 "       \
        "{%0,%1,%2,%3}, {%4,%5,%6,%7}, {%8,%9}, {%0,%1,%2,%3};"               \
        : "+f"((c)[0]), "+f"((c)[1]), "+f"((c)[2]), "+f"((c)[3])              \
        : "r"((a)[0]), "r"((a)[1]), "r"((a)[2]), "r"((a)[3]),                 \
          "r"((bb).x), "r"((bb).y))

// Load whole 64x64 input tile: thread = (row tid>>2, k-quarter tid&3), 16 consec k
#define LOADX(xptr)                                                           \
    do {                                                                      \
        const float4* _p4 = (const float4*)(xptr);                            \
        _Pragma("unroll")                                                     \
        for (int _j = 0; _j < 4; _j++) xr[_j] = _p4[xbase + _j];              \
    } while (0)

// exp + bf16-split + swizzled store of both planes (conflict-free STS.128)
#define CONV_INPUT()                                                          \
    do {                                                                      \
        const int _r = tid >> 2, _kq = tid & 3;                               \
        float _e[16];                                                         \
        _Pragma("unroll")                                                     \
        for (int _j = 0; _j < 4; _j++) {                                      \
            _e[4*_j+0] = __expf(xr[_j].x); _e[4*_j+1] = __expf(xr[_j].y);     \
            _e[4*_j+2] = __expf(xr[_j].z); _e[4*_j+3] = __expf(xr[_j].w);     \
        }                                                                     \
        _Pragma("unroll")                                                     \
        for (int _cc = 0; _cc < 2; _cc++) {                                   \
            uint4 _ub, _us;                                                   \
            _ub.x = split_pack(_e[_cc*8+0], _e[_cc*8+1], _us.x);              \
            _ub.y = split_pack(_e[_cc*8+2], _e[_cc*8+3], _us.y);              \
            _ub.z = split_pack(_e[_cc*8+4], _e[_cc*8+5], _us.z);              \
            _ub.w = split_pack(_e[_cc*8+6], _e[_cc*8+7], _us.w);              \
            const int _sw = (_kq * 2 + _cc) ^ (_r & 7);                       \
            *(uint4*)(smc + E_BYTE + _r * 128 + _sw * 16)        = _ub;       \
            *(uint4*)(smc + E_BYTE + 8192 + _r * 128 + _sw * 16) = _us;       \
        }                                                                     \
    } while (0)

// 3-term bf16 mma over K=64: acc[mt][nt][4]
#define MMA_GEMM()                                                            \
    do {                                                                      \
        _Pragma("unroll")                                                     \
        for (int _ks = 0; _ks < 4; _ks++) {                                   \
            const uint32_t _swz = (uint32_t)((((_ks*2 + lhi) ^ (lane & 7))) << 4); \
            uint32_t _ab[2][4], _as[2][4];                                    \
            _Pragma("unroll")                                                 \
            for (int _mt = 0; _mt < 2; _mt++) {                               \
                const uint32_t _adr = eb_u32 + (uint32_t)((lrow0 + _mt*16) * 128) + _swz; \
                LDM4(_ab[_mt], _adr);                                         \
                LDM4(_as[_mt], _adr + 8192);                                  \
            }                                                                 \
            _Pragma("unroll")                                                 \
            for (int _nt = 0; _nt < 4; _nt++) {                               \
                const uint2 _Bb = *(const uint2*)&smu[(_ks*16 + wn*4 + _nt)*64 + lane*2];       \
                const uint2 _Bs = *(const uint2*)&smu[((4+_ks)*16 + wn*4 + _nt)*64 + lane*2];   \
                _Pragma("unroll")                                             \
                for (int _mt = 0; _mt < 2; _mt++) {                           \
                    MMAB(acc[_mt][_nt], _ab[_mt], _Bb);                       \
                    MMAB(acc[_mt][_nt], _ab[_mt], _Bs);                       \
                    MMAB(acc[_mt][_nt], _as[_mt], _Bb);                       \
                }                                                             \
            }                                                                 \
        }                                                                     \
    } while (0)

#define ZEROACC()                                                             \
    do {                                                                      \
        _Pragma("unroll") for (int _m = 0; _m < 2; _m++)                      \
        _Pragma("unroll") for (int _n = 0; _n < 4; _n++)                      \
        _Pragma("unroll") for (int _i = 0; _i < 4; _i++) acc[_m][_n][_i] = 0.f; \
    } while (0)

// ---------------------------------------------------------------------------
// Fused: bf16 3-term mma.sync feature GEMMs + gates + chunked scan (decoupled
// lookback) + output. CTA = 64 s-rows x 128 F, 256 thr / 8 warps, 2 CTAs/SM.
// warp: wm = w>>2 (rows wm*32..+31 as 2 m16 tiles), wn = w&3 (cols wn*32..+31).
// ---------------------------------------------------------------------------
__global__ __launch_bounds__(256, 2)
void fused_sla(const float* __restrict__ q, const float* __restrict__ k,
               const float* __restrict__ v, float* __restrict__ out)
{
    extern __shared__ float sm[];
    uint32_t* smu = (uint32_t*)sm;
    char* smc = (char*)sm;
    const int tid = threadIdx.x, lane = tid & 31, w8 = tid >> 5;
    const int wn = w8 & 3, wm = w8 >> 2;
    const int group = lane >> 2, tig = lane & 3;
    const int lhi = (lane >> 4) & 1;
    const int lrow0 = wm * 32 + (lane & 7) + ((lane >> 3) & 1) * 8;
    const int b = blockIdx.x, ch = blockIdx.y;
    const int xbase = (tid >> 2) * 16 + (tid & 3) * 4;
    const size_t ibase = ((size_t)b * SS + ch * CS) * DD;
    const uint32_t eb_u32 = (uint32_t)__cvta_generic_to_shared(smc + E_BYTE);

    float4 xr[4];
    float acc[2][4][4];

    LOADX(v + ibase);
    // B fragments -> smem (coalesced)
#pragma unroll
    for (int t = 0; t < 8; t++)
        ((uint4*)smu)[tid + t * 256] = ((const uint4*)g_wfragB)[tid + t * 256];
    CONV_INPUT();                      // V -> E
    LOADX(k + ibase);
    __syncthreads();

    // ===== V GEMM -> v_f to SMV =====
    ZEROACC();
    MMA_GEMM();
#pragma unroll
    for (int mt = 0; mt < 2; mt++)
#pragma unroll
        for (int nt = 0; nt < 4; nt++) {
            const int col = wn * 32 + nt * 8 + tig * 2;
            const int rA = wm * 32 + mt * 16 + group;
            *(float2*)&sm[SMV + rA * 128 + col]       = make_float2(acc[mt][nt][0], acc[mt][nt][1]);
            *(float2*)&sm[SMV + (rA + 8) * 128 + col] = make_float2(acc[mt][nt][2], acc[mt][nt][3]);
        }
    __syncthreads();                   // E free

    CONV_INPUT();                      // K -> E
    LOADX(q + ibase);
    __syncthreads();

    // ===== K GEMM -> gate -> a (SMA), c = a*v_f (SMV) =====
    ZEROACC();
    MMA_GEMM();
#pragma unroll
    for (int mt = 0; mt < 2; mt++)
#pragma unroll
        for (int nt = 0; nt < 4; nt++) {
            const int col = wn * 32 + nt * 8 + tig * 2;
            const int rA = wm * 32 + mt * 16 + group;
            const float2 vf0 = *(const float2*)&sm[SMV + rA * 128 + col];
            const float2 vf1 = *(const float2*)&sm[SMV + (rA + 8) * 128 + col];
            const float a0 = GATE(acc[mt][nt][0]), a1 = GATE(acc[mt][nt][1]);
            const float a2 = GATE(acc[mt][nt][2]), a3 = GATE(acc[mt][nt][3]);
            *(float2*)&sm[SMA + rA * 128 + col]       = make_float2(a0, a1);
            *(float2*)&sm[SMA + (rA + 8) * 128 + col] = make_float2(a2, a3);
            *(float2*)&sm[SMV + rA * 128 + col]       = make_float2(a0 * vf0.x, a1 * vf0.y);
            *(float2*)&sm[SMV + (rA + 8) * 128 + col] = make_float2(a2 * vf1.x, a3 * vf1.y);
        }
    __syncthreads();                   // E free + SMA/SMV visible

    // ===== local cumsums (two 32-row halves per column, in place) =====
    {
        const int col = tid & 127;
        const int r0  = (tid >> 7) * 32;
        float cA = 0.f, cC = 0.f;
#pragma unroll 8
        for (int s = 0; s < 32; s++) {
            cA += sm[SMA + (r0 + s) * 128 + col];
            sm[SMA + (r0 + s) * 128 + col] = cA;
            cC += sm[SMV + (r0 + s) * 128 + col];
            sm[SMV + (r0 + s) * 128 + col] = cC;
        }
    }
    __syncthreads();

    // ===== publish aggregates, then stage Q =====
    if (tid < FF) {
        const float aggA = sm[SMA + 31 * 128 + tid] + sm[SMA + 63 * 128 + tid];
        const float aggC = sm[SMV + 31 * 128 + tid] + sm[SMV + 63 * 128 + tid];
        g_aggA[((size_t)ch * BB + b) * FF + tid] = aggA;
        g_aggC[((size_t)ch * BB + b) * FF + tid] = aggC;
        __threadfence();
    }
    CONV_INPUT();                      // Q -> E
    __syncthreads();
    if (tid == 0) atomicExch(&g_flag[ch * BB + b], 1);

    // ===== Q GEMM -> gated q_s in acc =====
    ZEROACC();
    MMA_GEMM();
#pragma unroll
    for (int mt = 0; mt < 2; mt++)
#pragma unroll
        for (int nt = 0; nt < 4; nt++)
#pragma unroll
            for (int i = 0; i < 4; i++)
                acc[mt][nt][i] = GATE(acc[mt][nt][i]);

    // ===== lookback wait (parallel) =====
    if (tid < ch)
        while (((volatile int*)g_flag)[tid * BB + b] == 0) __nanosleep(64);
    __syncthreads();                   // also: all warps done reading E

    // ===== prefix sums over predecessors -> prefbuf (reuses E) =====
    if (tid < FF) {
        float pA0 = 0.f, pA1 = 0.f, pC0 = 0.f, pC1 = 0.f;
        int p = 0;
        for (; p + 1 < ch; p += 2) {
            pA0 += g_aggA[((size_t)p * BB + b) * FF + tid];
            pA1 += g_aggA[((size_t)(p + 1) * BB + b) * FF + tid];
            pC0 += g_aggC[((size_t)p * BB + b) * FF + tid];
            pC1 += g_aggC[((size_t)(p + 1) * BB + b) * FF + tid];
        }
        if (p < ch) {
            pA0 += g_aggA[((size_t)p * BB + b) * FF + tid];
            pC0 += g_aggC[((size_t)p * BB + b) * FF + tid];
        }
        sm[SMPF  + tid] = pA0 + pA1;
        sm[SMPFC + tid] = pC0 + pC1;
    }
    __syncthreads();

    // ===== output: out = q_s * (prefC+cumC+eps)/(prefA+cumA+eps) =====
    const size_t ob = ((size_t)b * SS + ch * CS) * FF;
#pragma unroll
    for (int mt = 0; mt < 2; mt++)
#pragma unroll
        for (int nt = 0; nt < 4; nt++) {
            const int col = wn * 32 + nt * 8 + tig * 2;
            const int rA = wm * 32 + mt * 16 + group;
            float2 bA = *(const float2*)&sm[SMPF + col];
            float2 bC = *(const float2*)&sm[SMPFC + col];
            if (wm == 1) {   // upper half: add lower-half totals
                const float2 lA = *(const float2*)&sm[SMA + 31 * 128 + col];
                const float2 lC = *(const float2*)&sm[SMV + 31 * 128 + col];
                bA.x += lA.x; bA.y += lA.y;
                bC.x += lC.x; bC.y += lC.y;
            }
            const float2 a0 = *(const float2*)&sm[SMA + rA * 128 + col];
            const float2 a1 = *(const float2*)&sm[SMA + (rA + 8) * 128 + col];
            const float2 c0 = *(const float2*)&sm[SMV + rA * 128 + col];
            const float2 c1 = *(const float2*)&sm[SMV + (rA + 8) * 128 + col];
            float2 o0, o1;
            o0.x = acc[mt][nt][0] * __fdividef(bC.x + c0.x + 1e-8f, bA.x + a0.x + 1e-8f);
            o0.y = acc[mt][nt][1] * __fdividef(bC.y + c0.y + 1e-8f, bA.y + a0.y + 1e-8f);
            o1.x = acc[mt][nt][2] * __fdividef(bC.x + c1.x + 1e-8f, bA.x + a1.x + 1e-8f);
            o1.y = acc[mt][nt][3] * __fdividef(bC.y + c1.y + 1e-8f, bA.y + a1.y + 1e-8f);
            *(float2*)&out[ob + (size_t)rA * 128 + col]       = o0;
            *(float2*)&out[ob + (size_t)(rA + 8) * 128 + col] = o1;
        }
}

extern "C" void kernel_launch(void* const* d_in, const int* in_sizes, int n_in,
                              void* d_out, int out_size)
{
    const float* q = (const float*)d_in[0];
    const float* k = (const float*)d_in[1];
    const float* v = (const float*)d_in[2];
    const float* w = (const float*)d_in[3];
    float* out = (float*)d_out;

    zero_flags<<<(NCH * BB + 255) / 256, 256>>>();
    wfrag_setup<<<1, 256>>>(w);

    cudaFuncSetAttribute(fused_sla, cudaFuncAttributeMaxDynamicSharedMemorySize,
                         SM_FLOATS * 4);
    dim3 grid(BB, NCH);   // linear bid = ch*BB + b (chunk-major)
    fused_sla<<<grid, 256, SM_FLOATS * 4>>>(q, k, v, out);
}

// round 12
// speedup vs baseline: 1.2763x; 1.0118x over previous
#include <cuda_runtime.h>
#include <cstdint>

#define BB 32
#define SS 8192
#define DD 64
#define FF 128
#define CS 64
#define NCH (SS / CS)   // 128 chunks
#define PIT 130         // smem row pitch for SMA/SMV (bank-conflict-free)

// Cross-CTA scan state (flags zeroed each launch)
__device__ float    g_aggA[NCH * BB * FF];
__device__ float    g_aggC[NCH * BB * FF];
__device__ int      g_flag[NCH * BB];
__device__ uint32_t g_wfragB[8192];   // [plane][kstep][ntile][lane][reg] bf16x2

// pack (lo, hi) fp32 -> bf16x2 (lo in lower 16 bits)
__device__ __forceinline__ uint32_t bf16x2(float lo, float hi) {
    uint32_t r;
    asm("cvt.rn.bf16x2.f32 %0, %1, %2;" : "=r"(r) : "f"(hi), "f"(lo));
    return r;
}
// split: returns big bf16x2, writes residual bf16x2
__device__ __forceinline__ uint32_t split_pack(float e0, float e1, uint32_t& sres) {
    const uint32_t b = bf16x2(e0, e1);
    const float f0 = __uint_as_float(b << 16);
    const float f1 = __uint_as_float(b & 0xFFFF0000u);
    sres = bf16x2(e0 - f0, e1 - f1);
    return b;
}

// ---------------------------------------------------------------------------
// Combined setup: zero flags + W -> bf16 (big, small) B-fragments.
// ---------------------------------------------------------------------------
__global__ void setup_kernel(const float* __restrict__ w)
{
    const int i = blockIdx.x * 256 + threadIdx.x;
    if (i < NCH * BB) g_flag[i] = 0;
    const int o = i - NCH * BB;
    if (o >= 0 && o < 8192) {
        const int reg = o & 1, lane = (o >> 1) & 31, nt = (o >> 6) & 15;
        const int ks = (o >> 10) & 3, plane = (o >> 12) & 1;
        const int group = lane >> 2, tig = lane & 3;
        const int k0  = ks * 16 + tig * 2 + reg * 8;
        const int col = nt * 8 + group;
        const float v0 = w[k0 * FF + col];
        const float v1 = w[(k0 + 1) * FF + col];
        uint32_t s;
        const uint32_t b = split_pack(v0, v1, s);
        g_wfragB[o] = plane ? s : b;
    }
}

// SMEM word offsets (total 28928 words = 113 KB -> 2 CTAs/SM)
#define SM_WF 0        // B frags: 8192 u32 (32 KB)
#define SM_E  8192     // A staging: EB 2048 + ES 2048 u32 (16 KB, swizzled)
#define SMA   12288    // k_s -> cumsum: 64 x PIT f32
#define SMV   (12288 + 64 * PIT)   // v_f / c -> cumsum: 64 x PIT f32
#define SMPF  8192     // prefix A (reuses E after Q mma)
#define SMPFC 8320     // prefix C
#define SM_FLOATS (12288 + 128 * PIT)
#define E_BYTE (SM_E * 4)   // 32768

#define GATE(x) (((x) > 0.5f) ? (x) : 0.f)

#define LDM4(r, a)                                                            \
    asm volatile("ldmatrix.sync.aligned.m8n8.x4.shared.b16 {%0,%1,%2,%3}, [%4];" \
        : "=r"((r)[0]), "=r"((r)[1]), "=r"((r)[2]), "=r"((r)[3]) : "r"(a))

#define MMAB(c, a, bb)                                                        \
    asm volatile("mma.sync.aligned.m16n8k16.row.col.f32.bf16.bf16.f32 "       \
        "{%0,%1,%2,%3}, {%4,%5,%6,%7}, {%8,%9}, {%0,%1,%2,%3};"               \
        : "+f"((c)[0]), "+f"((c)[1]), "+f"((c)[2]), "+f"((c)[3])              \
        : "r"((a)[0]), "r"((a)[1]), "r"((a)[2]), "r"((a)[3]),                 \
          "r"((bb).x), "r"((bb).y))

// Load whole 64x64 input tile: thread = (row tid>>2, k-quarter tid&3)
#define LOADX(xptr)                                                           \
    do {                                                                      \
        const float4* _p4 = (const float4*)(xptr);                            \
        _Pragma("unroll")                                                     \
        for (int _j = 0; _j < 4; _j++) xr[_j] = _p4[xbase + _j];              \
    } while (0)

// exp + bf16-split + swizzled store of both planes (conflict-free STS.128)
#define CONV_INPUT()                                                          \
    do {                                                                      \
        const int _r = tid >> 2, _kq = tid & 3;                               \
        float _e[16];                                                         \
        _Pragma("unroll")                                                     \
        for (int _j = 0; _j < 4; _j++) {                                      \
            _e[4*_j+0] = __expf(xr[_j].x); _e[4*_j+1] = __expf(xr[_j].y);     \
            _e[4*_j+2] = __expf(xr[_j].z); _e[4*_j+3] = __expf(xr[_j].w);     \
        }                                                                     \
        _Pragma("unroll")                                                     \
        for (int _cc = 0; _cc < 2; _cc++) {                                   \
            uint4 _ub, _us;                                                   \
            _ub.x = split_pack(_e[_cc*8+0], _e[_cc*8+1], _us.x);              \
            _ub.y = split_pack(_e[_cc*8+2], _e[_cc*8+3], _us.y);              \
            _ub.z = split_pack(_e[_cc*8+4], _e[_cc*8+5], _us.z);              \
            _ub.w = split_pack(_e[_cc*8+6], _e[_cc*8+7], _us.w);              \
            const int _sw = (_kq * 2 + _cc) ^ (_r & 7);                       \
            *(uint4*)(smc + E_BYTE + _r * 128 + _sw * 16)        = _ub;       \
            *(uint4*)(smc + E_BYTE + 8192 + _r * 128 + _sw * 16) = _us;       \
        }                                                                     \
    } while (0)

// 3-term bf16 mma over K=64: acc[mt][nt][4]
#define MMA_GEMM()                                                            \
    do {                                                                      \
        _Pragma("unroll")                                                     \
        for (int _ks = 0; _ks < 4; _ks++) {                                   \
            const uint32_t _swz = (uint32_t)((((_ks*2 + lhi) ^ (lane & 7))) << 4); \
            uint32_t _ab[2][4], _as[2][4];                                    \
            _Pragma("unroll")                                                 \
            for (int _mt = 0; _mt < 2; _mt++) {                               \
                const uint32_t _adr = eb_u32 + (uint32_t)((lrow0 + _mt*16) * 128) + _swz; \
                LDM4(_ab[_mt], _adr);                                         \
                LDM4(_as[_mt], _adr + 8192);                                  \
            }                                                                 \
            _Pragma("unroll")                                                 \
            for (int _nt = 0; _nt < 4; _nt++) {                               \
                const uint2 _Bb = *(const uint2*)&smu[(_ks*16 + wn*4 + _nt)*64 + lane*2];       \
                const uint2 _Bs = *(const uint2*)&smu[((4+_ks)*16 + wn*4 + _nt)*64 + lane*2];   \
                _Pragma("unroll")                                             \
                for (int _mt = 0; _mt < 2; _mt++) {                           \
                    MMAB(acc[_mt][_nt], _ab[_mt], _Bb);                       \
                    MMAB(acc[_mt][_nt], _ab[_mt], _Bs);                       \
                    MMAB(acc[_mt][_nt], _as[_mt], _Bb);                       \
                }                                                             \
            }                                                                 \
        }                                                                     \
    } while (0)

#define ZEROACC()                                                             \
    do {                                                                      \
        _Pragma("unroll") for (int _m = 0; _m < 2; _m++)                      \
        _Pragma("unroll") for (int _n = 0; _n < 4; _n++)                      \
        _Pragma("unroll") for (int _i = 0; _i < 4; _i++) acc[_m][_n][_i] = 0.f; \
    } while (0)

// ---------------------------------------------------------------------------
// Fused: bf16 3-term mma.sync feature GEMMs + gates + chunked scan (decoupled
// lookback) + output. CTA = 64 s-rows x 128 F, 256 thr / 8 warps, 2 CTAs/SM.
// ---------------------------------------------------------------------------
__global__ __launch_bounds__(256, 2)
void fused_sla(const float* __restrict__ q, const float* __restrict__ k,
               const float* __restrict__ v, float* __restrict__ out)
{
    extern __shared__ float sm[];
    uint32_t* smu = (uint32_t*)sm;
    char* smc = (char*)sm;
    const int tid = threadIdx.x, lane = tid & 31, w8 = tid >> 5;
    const int wn = w8 & 3, wm = w8 >> 2;
    const int group = lane >> 2, tig = lane & 3;
    const int lhi = (lane >> 4) & 1;
    const int lrow0 = wm * 32 + (lane & 7) + ((lane >> 3) & 1) * 8;
    const int b = blockIdx.x, ch = blockIdx.y;
    const int xbase = (tid >> 2) * 16 + (tid & 3) * 4;
    const size_t ibase = ((size_t)b * SS + ch * CS) * DD;
    const uint32_t eb_u32 = (uint32_t)__cvta_generic_to_shared(smc + E_BYTE);

    float4 xr[4];
    float acc[2][4][4];

    LOADX(v + ibase);
    // B fragments -> smem (coalesced)
#pragma unroll
    for (int t = 0; t < 8; t++)
        ((uint4*)smu)[tid + t * 256] = ((const uint4*)g_wfragB)[tid + t * 256];
    CONV_INPUT();                      // V -> E
    LOADX(k + ibase);
    __syncthreads();

    // ===== V GEMM -> v_f to SMV =====
    ZEROACC();
    MMA_GEMM();
#pragma unroll
    for (int mt = 0; mt < 2; mt++)
#pragma unroll
        for (int nt = 0; nt < 4; nt++) {
            const int col = wn * 32 + nt * 8 + tig * 2;
            const int rA = wm * 32 + mt * 16 + group;
            *(float2*)&sm[SMV + rA * PIT + col]       = make_float2(acc[mt][nt][0], acc[mt][nt][1]);
            *(float2*)&sm[SMV + (rA + 8) * PIT + col] = make_float2(acc[mt][nt][2], acc[mt][nt][3]);
        }
    __syncthreads();                   // E free

    CONV_INPUT();                      // K -> E
    LOADX(q + ibase);
    __syncthreads();

    // ===== K GEMM -> gate -> a (SMA), c = a*v_f (SMV) =====
    ZEROACC();
    MMA_GEMM();
#pragma unroll
    for (int mt = 0; mt < 2; mt++)
#pragma unroll
        for (int nt = 0; nt < 4; nt++) {
            const int col = wn * 32 + nt * 8 + tig * 2;
            const int rA = wm * 32 + mt * 16 + group;
            const float2 vf0 = *(const float2*)&sm[SMV + rA * PIT + col];
            const float2 vf1 = *(const float2*)&sm[SMV + (rA + 8) * PIT + col];
            const float a0 = GATE(acc[mt][nt][0]), a1 = GATE(acc[mt][nt][1]);
            const float a2 = GATE(acc[mt][nt][2]), a3 = GATE(acc[mt][nt][3]);
            *(float2*)&sm[SMA + rA * PIT + col]       = make_float2(a0, a1);
            *(float2*)&sm[SMA + (rA + 8) * PIT + col] = make_float2(a2, a3);
            *(float2*)&sm[SMV + rA * PIT + col]       = make_float2(a0 * vf0.x, a1 * vf0.y);
            *(float2*)&sm[SMV + (rA + 8) * PIT + col] = make_float2(a2 * vf1.x, a3 * vf1.y);
        }
    __syncthreads();

    // ===== local cumsums (two 32-row halves per column, in place) =====
    {
        const int col = tid & 127;
        const int r0  = (tid >> 7) * 32;
        float cA = 0.f, cC = 0.f;
#pragma unroll 8
        for (int s = 0; s < 32; s++) {
            cA += sm[SMA + (r0 + s) * PIT + col];
            sm[SMA + (r0 + s) * PIT + col] = cA;
            cC += sm[SMV + (r0 + s) * PIT + col];
            sm[SMV + (r0 + s) * PIT + col] = cC;
        }
    }
    __syncthreads();

    // ===== publish aggregates, then stage Q =====
    if (tid < FF) {
        const float aggA = sm[SMA + 31 * PIT + tid] + sm[SMA + 63 * PIT + tid];
        const float aggC = sm[SMV + 31 * PIT + tid] + sm[SMV + 63 * PIT + tid];
        g_aggA[((size_t)ch * BB + b) * FF + tid] = aggA;
        g_aggC[((size_t)ch * BB + b) * FF + tid] = aggC;
        __threadfence();
    }
    CONV_INPUT();                      // Q -> E
    __syncthreads();
    if (tid == 0) atomicExch(&g_flag[ch * BB + b], 1);

    // ===== Q GEMM -> gated q_s in acc =====
    ZEROACC();
    MMA_GEMM();
#pragma unroll
    for (int mt = 0; mt < 2; mt++)
#pragma unroll
        for (int nt = 0; nt < 4; nt++)
#pragma unroll
            for (int i = 0; i < 4; i++)
                acc[mt][nt][i] = GATE(acc[mt][nt][i]);

    // ===== lookback wait (parallel) =====
    if (tid < ch)
        while (((volatile int*)g_flag)[tid * BB + b] == 0) __nanosleep(64);
    __syncthreads();                   // all warps done reading E

    // ===== prefix sums over predecessors -> prefbuf (reuses E) =====
    if (tid < FF) {
        float pA0 = 0.f, pA1 = 0.f, pC0 = 0.f, pC1 = 0.f;
        int p = 0;
        for (; p + 1 < ch; p += 2) {
            pA0 += g_aggA[((size_t)p * BB + b) * FF + tid];
            pA1 += g_aggA[((size_t)(p + 1) * BB + b) * FF + tid];
            pC0 += g_aggC[((size_t)p * BB + b) * FF + tid];
            pC1 += g_aggC[((size_t)(p + 1) * BB + b) * FF + tid];
        }
        if (p < ch) {
            pA0 += g_aggA[((size_t)p * BB + b) * FF + tid];
            pC0 += g_aggC[((size_t)p * BB + b) * FF + tid];
        }
        sm[SMPF  + tid] = pA0 + pA1;
        sm[SMPFC + tid] = pC0 + pC1;
    }
    __syncthreads();

    // ===== output: out = q_s * (prefC+cumC+eps)/(prefA+cumA+eps) =====
    const size_t ob = ((size_t)b * SS + ch * CS) * FF;
#pragma unroll
    for (int mt = 0; mt < 2; mt++)
#pragma unroll
        for (int nt = 0; nt < 4; nt++) {
            const int col = wn * 32 + nt * 8 + tig * 2;
            const int rA = wm * 32 + mt * 16 + group;
            float2 bA = *(const float2*)&sm[SMPF + col];
            float2 bC = *(const float2*)&sm[SMPFC + col];
            if (wm == 1) {   // upper half: add lower-half totals
                const float2 lA = *(const float2*)&sm[SMA + 31 * PIT + col];
                const float2 lC = *(const float2*)&sm[SMV + 31 * PIT + col];
                bA.x += lA.x; bA.y += lA.y;
                bC.x += lC.x; bC.y += lC.y;
            }
            const float2 a0 = *(const float2*)&sm[SMA + rA * PIT + col];
            const float2 a1 = *(const float2*)&sm[SMA + (rA + 8) * PIT + col];
            const float2 c0 = *(const float2*)&sm[SMV + rA * PIT + col];
            const float2 c1 = *(const float2*)&sm[SMV + (rA + 8) * PIT + col];
            float2 o0, o1;
            o0.x = acc[mt][nt][0] * __fdividef(bC.x + c0.x + 1e-8f, bA.x + a0.x + 1e-8f);
            o0.y = acc[mt][nt][1] * __fdividef(bC.y + c0.y + 1e-8f, bA.y + a0.y + 1e-8f);
            o1.x = acc[mt][nt][2] * __fdividef(bC.x + c1.x + 1e-8f, bA.x + a1.x + 1e-8f);
            o1.y = acc[mt][nt][3] * __fdividef(bC.y + c1.y + 1e-8f, bA.y + a1.y + 1e-8f);
            *(float2*)&out[ob + (size_t)rA * FF + col]       = o0;
            *(float2*)&out[ob + (size_t)(rA + 8) * FF + col] = o1;
        }
}

extern "C" void kernel_launch(void* const* d_in, const int* in_sizes, int n_in,
                              void* d_out, int out_size)
{
    const float* q = (const float*)d_in[0];
    const float* k = (const float*)d_in[1];
    const float* v = (const float*)d_in[2];
    const float* w = (const float*)d_in[3];
    float* out = (float*)d_out;

    setup_kernel<<<(NCH * BB + 8192 + 255) / 256, 256>>>(w);

    cudaFuncSetAttribute(fused_sla, cudaFuncAttributeMaxDynamicSharedMemorySize,
                         SM_FLOATS * 4);
    dim3 grid(BB, NCH);   // linear bid = ch*BB + b (chunk-major)
    fused_sla<<<grid, 256, SM_FLOATS * 4>>>(q, k, v, out);
}

// round 13
// speedup vs baseline: 1.5151x; 1.1871x over previous
#include <cuda_runtime.h>
#include <cstdint>

#define BB 32
#define SS 8192
#define DD 64
#define FF 128
#define CS 64
#define NCH (SS / CS)   // 128 chunks

// Cross-CTA scan state (flags zeroed each launch)
__device__ float    g_aggA[NCH * BB * FF];
__device__ float    g_aggC[NCH * BB * FF];
__device__ int      g_flag[NCH * BB];
__device__ uint32_t g_wfragB[8192];   // [plane][kstep][ntile][lane][reg] bf16x2

// pack (lo, hi) fp32 -> bf16x2 (lo in lower 16 bits)
__device__ __forceinline__ uint32_t bf16x2(float lo, float hi) {
    uint32_t r;
    asm("cvt.rn.bf16x2.f32 %0, %1, %2;" : "=r"(r) : "f"(hi), "f"(lo));
    return r;
}
// split: returns big bf16x2, writes residual bf16x2
__device__ __forceinline__ uint32_t split_pack(float e0, float e1, uint32_t& sres) {
    const uint32_t b = bf16x2(e0, e1);
    const float f0 = __uint_as_float(b << 16);
    const float f1 = __uint_as_float(b & 0xFFFF0000u);
    sres = bf16x2(e0 - f0, e1 - f1);
    return b;
}

// ---------------------------------------------------------------------------
// Combined setup: zero flags + W -> bf16 (big, small) B-fragments.
// ---------------------------------------------------------------------------
__global__ void setup_kernel(const float* __restrict__ w)
{
    const int i = blockIdx.x * 256 + threadIdx.x;
    if (i < NCH * BB) g_flag[i] = 0;
    const int o = i - NCH * BB;
    if (o >= 0 && o < 8192) {
        const int reg = o & 1, lane = (o >> 1) & 31, nt = (o >> 6) & 15;
        const int ks = (o >> 10) & 3, plane = (o >> 12) & 1;
        const int group = lane >> 2, tig = lane & 3;
        const int k0  = ks * 16 + tig * 2 + reg * 8;
        const int col = nt * 8 + group;
        const float v0 = w[k0 * FF + col];
        const float v1 = w[(k0 + 1) * FF + col];
        uint32_t s;
        const uint32_t b = split_pack(v0, v1, s);
        g_wfragB[o] = plane ? s : b;
    }
}

// SMEM word offsets (total 28672 words = 112 KB -> 2 CTAs/SM)
#define SM_WF 0        // B frags: 8192 u32 (32 KB)
#define SM_E  8192     // A staging: EB 2048 + ES 2048 u32 (16 KB, swizzled)
#define SMA   12288    // k_s -> cumsum: 64 x 128, XOR-swizzled cols
#define SMV   20480    // v_f / c -> cumsum: 64 x 128, XOR-swizzled cols
#define SMPF  8192     // prefix A half0/half1 (reuses E after Q mma): 256
#define SMPFC 8448     // prefix C half0/half1: 256
#define SM_FLOATS 28672
#define E_BYTE (SM_E * 4)   // 32768

// Bank-optimal column swizzle: element (row, col) at row*128 + (col ^ ((row&7)<<2))
#define SW(r, c) (((r) * 128) + ((c) ^ (((r) & 7) << 2)))

#define GATE(x) (((x) > 0.5f) ? (x) : 0.f)

#define LDM4(r, a)                                                            \
    asm volatile("ldmatrix.sync.aligned.m8n8.x4.shared.b16 {%0,%1,%2,%3}, [%4];" \
        : "=r"((r)[0]), "=r"((r)[1]), "=r"((r)[2]), "=r"((r)[3]) : "r"(a))

#define MMAB(c, a, bb)                                                        \
    asm volatile("mma.sync.aligned.m16n8k16.row.col.f32.bf16.bf16.f32 "       \
        "{%0,%1,%2,%3}, {%4,%5,%6,%7}, {%8,%9}, {%0,%1,%2,%3};"               \
        : "+f"((c)[0]), "+f"((c)[1]), "+f"((c)[2]), "+f"((c)[3])              \
        : "r"((a)[0]), "r"((a)[1]), "r"((a)[2]), "r"((a)[3]),                 \
          "r"((bb).x), "r"((bb).y))

// Load whole 64x64 input tile: thread = (row tid>>2, k-quarter tid&3)
#define LOADX(xptr)                                                           \
    do {                                                                      \
        const float4* _p4 = (const float4*)(xptr);                            \
        _Pragma("unroll")                                                     \
        for (int _j = 0; _j < 4; _j++) xr[_j] = _p4[xbase + _j];              \
    } while (0)

// exp + bf16-split + swizzled store of both planes (conflict-free STS.128)
#define CONV_INPUT()                                                          \
    do {                                                                      \
        const int _r = tid >> 2, _kq = tid & 3;                               \
        float _e[16];                                                         \
        _Pragma("unroll")                                                     \
        for (int _j = 0; _j < 4; _j++) {                                      \
            _e[4*_j+0] = __expf(xr[_j].x); _e[4*_j+1] = __expf(xr[_j].y);     \
            _e[4*_j+2] = __expf(xr[_j].z); _e[4*_j+3] = __expf(xr[_j].w);     \
        }                                                                     \
        _Pragma("unroll")                                                     \
        for (int _cc = 0; _cc < 2; _cc++) {                                   \
            uint4 _ub, _us;                                                   \
            _ub.x = split_pack(_e[_cc*8+0], _e[_cc*8+1], _us.x);              \
            _ub.y = split_pack(_e[_cc*8+2], _e[_cc*8+3], _us.y);              \
            _ub.z = split_pack(_e[_cc*8+4], _e[_cc*8+5], _us.z);              \
            _ub.w = split_pack(_e[_cc*8+6], _e[_cc*8+7], _us.w);              \
            const int _sw = (_kq * 2 + _cc) ^ (_r & 7);                       \
            *(uint4*)(smc + E_BYTE + _r * 128 + _sw * 16)        = _ub;       \
            *(uint4*)(smc + E_BYTE + 8192 + _r * 128 + _sw * 16) = _us;       \
        }                                                                     \
    } while (0)

// 3-term bf16 mma over K=64: acc[mt][nt][4]
#define MMA_GEMM()                                                            \
    do {                                                                      \
        _Pragma("unroll")                                                     \
        for (int _ks = 0; _ks < 4; _ks++) {                                   \
            const uint32_t _swz = (uint32_t)((((_ks*2 + lhi) ^ (lane & 7))) << 4); \
            uint32_t _ab[2][4], _as[2][4];                                    \
            _Pragma("unroll")                                                 \
            for (int _mt = 0; _mt < 2; _mt++) {                               \
                const uint32_t _adr = eb_u32 + (uint32_t)((lrow0 + _mt*16) * 128) + _swz; \
                LDM4(_ab[_mt], _adr);                                         \
                LDM4(_as[_mt], _adr + 8192);                                  \
            }                                                                 \
            _Pragma("unroll")                                                 \
            for (int _nt = 0; _nt < 4; _nt++) {                               \
                const uint2 _Bb = *(const uint2*)&smu[(_ks*16 + wn*4 + _nt)*64 + lane*2];       \
                const uint2 _Bs = *(const uint2*)&smu[((4+_ks)*16 + wn*4 + _nt)*64 + lane*2];   \
                _Pragma("unroll")                                             \
                for (int _mt = 0; _mt < 2; _mt++) {                           \
                    MMAB(acc[_mt][_nt], _ab[_mt], _Bb);                       \
                    MMAB(acc[_mt][_nt], _ab[_mt], _Bs);                       \
                    MMAB(acc[_mt][_nt], _as[_mt], _Bb);                       \
                }                                                             \
            }                                                                 \
        }                                                                     \
    } while (0)

#define ZEROACC()                                                             \
    do {                                                                      \
        _Pragma("unroll") for (int _m = 0; _m < 2; _m++)                      \
        _Pragma("unroll") for (int _n = 0; _n < 4; _n++)                      \
        _Pragma("unroll") for (int _i = 0; _i < 4; _i++) acc[_m][_n][_i] = 0.f; \
    } while (0)

// ---------------------------------------------------------------------------
// Fused: bf16 3-term mma.sync feature GEMMs + gates + chunked scan (decoupled
// lookback) + output. CTA = 64 s-rows x 128 F, 256 thr / 8 warps, 2 CTAs/SM.
// ---------------------------------------------------------------------------
__global__ __launch_bounds__(256, 2)
void fused_sla(const float* __restrict__ q, const float* __restrict__ k,
               const float* __restrict__ v, float* __restrict__ out)
{
    extern __shared__ float sm[];
    uint32_t* smu = (uint32_t*)sm;
    char* smc = (char*)sm;
    const int tid = threadIdx.x, lane = tid & 31, w8 = tid >> 5;
    const int wn = w8 & 3, wm = w8 >> 2;
    const int group = lane >> 2, tig = lane & 3;
    const int lhi = (lane >> 4) & 1;
    const int lrow0 = wm * 32 + (lane & 7) + ((lane >> 3) & 1) * 8;
    const int b = blockIdx.x, ch = blockIdx.y;
    const int xbase = (tid >> 2) * 16 + (tid & 3) * 4;
    const size_t ibase = ((size_t)b * SS + ch * CS) * DD;
    const uint32_t eb_u32 = (uint32_t)__cvta_generic_to_shared(smc + E_BYTE);

    float4 xr[4];
    float acc[2][4][4];

    LOADX(v + ibase);
    // B fragments -> smem (coalesced)
#pragma unroll
    for (int t = 0; t < 8; t++)
        ((uint4*)smu)[tid + t * 256] = ((const uint4*)g_wfragB)[tid + t * 256];
    CONV_INPUT();                      // V -> E
    LOADX(k + ibase);
    __syncthreads();

    // ===== V GEMM -> v_f to SMV =====
    ZEROACC();
    MMA_GEMM();
#pragma unroll
    for (int mt = 0; mt < 2; mt++)
#pragma unroll
        for (int nt = 0; nt < 4; nt++) {
            const int col = wn * 32 + nt * 8 + tig * 2;
            const int cs  = col ^ (group << 2);        // rA&7 == group
            const int rA = wm * 32 + mt * 16 + group;
            *(float2*)&sm[SMV + rA * 128 + cs]       = make_float2(acc[mt][nt][0], acc[mt][nt][1]);
            *(float2*)&sm[SMV + (rA + 8) * 128 + cs] = make_float2(acc[mt][nt][2], acc[mt][nt][3]);
        }
    __syncthreads();                   // E free

    CONV_INPUT();                      // K -> E
    LOADX(q + ibase);
    __syncthreads();

    // ===== K GEMM -> gate -> a (SMA), c = a*v_f (SMV) =====
    ZEROACC();
    MMA_GEMM();
#pragma unroll
    for (int mt = 0; mt < 2; mt++)
#pragma unroll
        for (int nt = 0; nt < 4; nt++) {
            const int col = wn * 32 + nt * 8 + tig * 2;
            const int cs  = col ^ (group << 2);
            const int rA = wm * 32 + mt * 16 + group;
            const float2 vf0 = *(const float2*)&sm[SMV + rA * 128 + cs];
            const float2 vf1 = *(const float2*)&sm[SMV + (rA + 8) * 128 + cs];
            const float a0 = GATE(acc[mt][nt][0]), a1 = GATE(acc[mt][nt][1]);
            const float a2 = GATE(acc[mt][nt][2]), a3 = GATE(acc[mt][nt][3]);
            *(float2*)&sm[SMA + rA * 128 + cs]       = make_float2(a0, a1);
            *(float2*)&sm[SMA + (rA + 8) * 128 + cs] = make_float2(a2, a3);
            *(float2*)&sm[SMV + rA * 128 + cs]       = make_float2(a0 * vf0.x, a1 * vf0.y);
            *(float2*)&sm[SMV + (rA + 8) * 128 + cs] = make_float2(a2 * vf1.x, a3 * vf1.y);
        }
    __syncthreads();

    // ===== local cumsums (two 32-row halves per column, in place) =====
    {
        const int col = tid & 127;
        const int r0  = (tid >> 7) * 32;
        float cA = 0.f, cC = 0.f;
#pragma unroll
        for (int so = 0; so < 32; so += 8)
#pragma unroll
            for (int si = 0; si < 8; si++) {
                const int idx = (r0 + so + si) * 128 + (col ^ (si << 2));
                cA += sm[SMA + idx];
                sm[SMA + idx] = cA;
                cC += sm[SMV + idx];
                sm[SMV + idx] = cC;
            }
    }
    __syncthreads();

    // ===== publish aggregates, then stage Q =====
    if (tid < FF) {
        const int cs28 = tid ^ 28;     // rows 31, 63: (r&7)=7 -> XOR 28
        const float aggA = sm[SMA + 31 * 128 + cs28] + sm[SMA + 63 * 128 + cs28];
        const float aggC = sm[SMV + 31 * 128 + cs28] + sm[SMV + 63 * 128 + cs28];
        g_aggA[((size_t)ch * BB + b) * FF + tid] = aggA;
        g_aggC[((size_t)ch * BB + b) * FF + tid] = aggC;
        __threadfence();
    }
    CONV_INPUT();                      // Q -> E
    __syncthreads();
    if (tid == 0) atomicExch(&g_flag[ch * BB + b], 1);

    // ===== Q GEMM -> gated q_s in acc =====
    ZEROACC();
    MMA_GEMM();
#pragma unroll
    for (int mt = 0; mt < 2; mt++)
#pragma unroll
        for (int nt = 0; nt < 4; nt++)
#pragma unroll
            for (int i = 0; i < 4; i++)
                acc[mt][nt][i] = GATE(acc[mt][nt][i]);

    // ===== lookback wait (parallel) =====
    if (tid < ch)
        while (((volatile int*)g_flag)[tid * BB + b] == 0) __nanosleep(64);
    __syncthreads();                   // all warps done reading E

    // ===== prefix sums over predecessors, split across all 256 threads =====
    {
        const int colp  = tid & 127;
        const int half  = tid >> 7;
        const int pbeg  = half ? (ch >> 1) : 0;
        const int pend  = half ? ch : (ch >> 1);
        float pA = 0.f, pC = 0.f;
#pragma unroll 4
        for (int p = pbeg; p < pend; p++) {
            pA += g_aggA[((size_t)p * BB + b) * FF + colp];
            pC += g_aggC[((size_t)p * BB + b) * FF + colp];
        }
        sm[SMPF  + half * 128 + colp] = pA;
        sm[SMPFC + half * 128 + colp] = pC;
    }
    __syncthreads();

    // ===== output: out = q_s * (prefC+cumC+eps)/(prefA+cumA+eps) =====
    const size_t ob = ((size_t)b * SS + ch * CS) * FF;
#pragma unroll
    for (int mt = 0; mt < 2; mt++)
#pragma unroll
        for (int nt = 0; nt < 4; nt++) {
            const int col = wn * 32 + nt * 8 + tig * 2;
            const int cs  = col ^ (group << 2);
            const int rA = wm * 32 + mt * 16 + group;
            const float2 pf0A = *(const float2*)&sm[SMPF + col];
            const float2 pf1A = *(const float2*)&sm[SMPF + 128 + col];
            const float2 pf0C = *(const float2*)&sm[SMPFC + col];
            const float2 pf1C = *(const float2*)&sm[SMPFC + 128 + col];
            float2 bA = make_float2(pf0A.x + pf1A.x, pf0A.y + pf1A.y);
            float2 bC = make_float2(pf0C.x + pf1C.x, pf0C.y + pf1C.y);
            if (wm == 1) {   // upper half: add lower-half totals (row 31 -> XOR 28)
                const float2 lA = *(const float2*)&sm[SMA + 31 * 128 + (col ^ 28)];
                const float2 lC = *(const float2*)&sm[SMV + 31 * 128 + (col ^ 28)];
                bA.x += lA.x; bA.y += lA.y;
                bC.x += lC.x; bC.y += lC.y;
            }
            const float2 a0 = *(const float2*)&sm[SMA + rA * 128 + cs];
            const float2 a1 = *(const float2*)&sm[SMA + (rA + 8) * 128 + cs];
            const float2 c0 = *(const float2*)&sm[SMV + rA * 128 + cs];
            const float2 c1 = *(const float2*)&sm[SMV + (rA + 8) * 128 + cs];
            float2 o0, o1;
            o0.x = acc[mt][nt][0] * __fdividef(bC.x + c0.x + 1e-8f, bA.x + a0.x + 1e-8f);
            o0.y = acc[mt][nt][1] * __fdividef(bC.y + c0.y + 1e-8f, bA.y + a0.y + 1e-8f);
            o1.x = acc[mt][nt][2] * __fdividef(bC.x + c1.x + 1e-8f, bA.x + a1.x + 1e-8f);
            o1.y = acc[mt][nt][3] * __fdividef(bC.y + c1.y + 1e-8f, bA.y + a1.y + 1e-8f);
            *(float2*)&out[ob + (size_t)rA * FF + col]       = o0;
            *(float2*)&out[ob + (size_t)(rA + 8) * FF + col] = o1;
        }
}

extern "C" void kernel_launch(void* const* d_in, const int* in_sizes, int n_in,
                              void* d_out, int out_size)
{
    const float* q = (const float*)d_in[0];
    const float* k = (const float*)d_in[1];
    const float* v = (const float*)d_in[2];
    const float* w = (const float*)d_in[3];
    float* out = (float*)d_out;

    setup_kernel<<<(NCH * BB + 8192 + 255) / 256, 256>>>(w);

    cudaFuncSetAttribute(fused_sla, cudaFuncAttributeMaxDynamicSharedMemorySize,
                         SM_FLOATS * 4);
    dim3 grid(BB, NCH);   // linear bid = ch*BB + b (chunk-major)
    fused_sla<<<grid, 256, SM_FLOATS * 4>>>(q, k, v, out);
}